// round 16
// baseline (speedup 1.0000x reference)
#include <cuda_runtime.h>
#include <cstdint>

// ---------------- problem constants ----------------
constexpr int B  = 2;
constexpr int C  = 16;
constexpr int H  = 384;
constexpr int W  = 1280;
constexpr int Ht = 96;
constexpr int Wt = 320;
constexpr int HW   = H * W;
constexpr int FULL = B * H * W;
constexpr int TIL  = Ht * Wt;
constexpr int NT   = B * TIL;
constexpr int Hp = 48, Wp = 160;
// padded tile-res planes for the conv trunk (zero halo)
constexpr int PW = Wt + 2;           // 322
constexpr int PH = Ht + 2;           // 98
constexpr int PS = PH * PW;          // 31556

// ---------------- scratch ----------------
__device__ float g_upprev[B * 16 * TIL];
__device__ float g_sumabs[FULL];
__device__ float g_cv[6][FULL];
__device__ float g_hA[B * 32 * PS];   // padded
__device__ float g_hB[B * 32 * PS];   // padded
__device__ float g_hC[B * 32 * PS];   // padded
__device__ float g_u[B * 34 * TIL];   // flat
// transposed weights scratch: 4 convs of 2*288*16 + 1 conv of 2*288*20
__device__ float g_wt[4 * 9216 + 11520];

// constant weight bank for the CURRENT conv (rewritten between launches)
// layout: [slice][ci*9+tap][OCB] viewed as ulonglong2 (4 floats each)
__constant__ ulonglong2 c_w2[2 * 288 * 20 / 4];   // 46080 B

// ---------------- f32x2 packed helpers ----------------
__device__ __forceinline__ void ffma2(uint64_t& d, uint64_t a, uint64_t b) {
    asm("fma.rn.f32x2 %0, %1, %2, %0;" : "+l"(d) : "l"(a), "l"(b));
}
__device__ __forceinline__ uint64_t pack2(float lo, float hi) {
    uint64_t r;
    asm("mov.b64 %0, {%1, %2};" : "=l"(r) : "f"(lo), "f"(hi));
    return r;
}
__device__ __forceinline__ uint64_t bcast2(float v) {
    uint64_t r;
    asm("mov.b64 %0, {%1, %1};" : "=l"(r) : "f"(v));
    return r;
}
__device__ __forceinline__ void unpack2(uint64_t a, float& lo, float& hi) {
    asm("mov.b64 {%0, %1}, %2;" : "=f"(lo), "=f"(hi) : "l"(a));
}

// ---------------- kernel 0: weight transpose ----------------
// scratch layout per conv: [slice][ci*9+tap][OCB], OCB-contiguous
__global__ void k_wtrans(const float* __restrict__ w, int OCT, int OCB, int off) {
    int t = blockIdx.x * blockDim.x + threadIdx.x;
    int total = 2 * 288 * OCB;
    if (t >= total) return;
    int slice = t / (288 * OCB);
    int rem = t % (288 * OCB);
    int ct = rem / OCB;       // ci*9 + tap
    int o = rem % OCB;
    int o_base = min(slice * OCB, OCT - OCB);
    g_wt[off + t] = w[(o_base + o) * 288 + ct];
}

// ---------------- kernel 1: upsample ----------------
__global__ void k_upsample(const float* __restrict__ prev) {
    int idx = blockIdx.x * blockDim.x + threadIdx.x;
    if (idx >= B * 16 * TIL) return;
    int x = idx % Wt;
    int y = (idx / Wt) % Ht;
    int c = (idx / TIL) % 16;
    int b = idx / (16 * TIL);
    int xh = x >> 1, yh = y >> 1;
    const float* p = prev + (size_t)b * 16 * Hp * Wp;
    int off = yh * Wp + xh;
    float v;
    if (c == 0) {
        float cx = (x & 1) ? 0.5f : -0.5f;
        float cy = (y & 1) ? 0.5f : -0.5f;
        v = 2.0f * (p[off] + cx * p[Hp * Wp + off] + cy * p[2 * Hp * Wp + off]);
    } else {
        v = p[c * Hp * Wp + off];
    }
    g_upprev[idx] = v;
}

// ---------------- kernel 2: fused fea + 6 cost volumes (shared gathers) ------
__global__ __launch_bounds__(128) void k_warpcv(const float* __restrict__ fea_l,
                                                const float* __restrict__ fea_r,
                                                const float* __restrict__ cur) {
    int idx = blockIdx.x * blockDim.x + threadIdx.x;
    if (idx >= FULL) return;
    int x = idx % W;
    int y = (idx / W) % H;
    int b = idx / (H * W);
    int ht = y >> 2, wt = x >> 2;
    float cx = (float)(x & 3) - 1.5f;
    float cy = (float)(y & 3) - 1.5f;

    int toff = b * 16 * TIL + ht * Wt + wt;
    float bc = cur[toff] + cx * cur[toff + TIL] + cy * cur[toff + 2 * TIL];
    float bp = g_upprev[toff] + cx * g_upprev[toff + TIL] + cy * g_upprev[toff + 2 * TIL];

    int   ic[4], ip[4];
    float ac_[4], bc_[4], apw[4], bpw[4];
    {
        float ix = (float)x - bc;
        float f = floorf(ix);
        float wx = ix - f;
        int x0 = (int)f;
#pragma unroll
        for (int t = 0; t < 4; t++) {
            int xi = x0 - 1 + t;
            float ok = (xi >= 0 && xi < W) ? 1.f : 0.f;
            ic[t] = min(max(xi, 0), W - 1);
            ac_[t] = (1.f - wx) * ok;
            bc_[t] = wx * ok;
        }
    }
    {
        float ix = (float)x - bp;
        float f = floorf(ix);
        float wx = ix - f;
        int x0 = (int)f;
#pragma unroll
        for (int t = 0; t < 4; t++) {
            int xi = x0 - 1 + t;
            float ok = (xi >= 0 && xi < W) ? 1.f : 0.f;
            ip[t] = min(max(xi, 0), W - 1);
            apw[t] = (1.f - wx) * ok;
            bpw[t] = wx * ok;
        }
    }

    float acc[6] = {0.f, 0.f, 0.f, 0.f, 0.f, 0.f};
    float sa = 0.f;
    const float* fl = fea_l + (size_t)b * C * HW + y * W + x;
    const float* fr = fea_r + (size_t)b * C * HW + y * W;
#pragma unroll 2
    for (int c = 0; c < C; c++) {
        float l = fl[c * HW];
        sa += fabsf(l);
        const float* r = fr + c * HW;
        float vc[4], vp[4];
#pragma unroll
        for (int t = 0; t < 4; t++) {
            vc[t] = __ldg(r + ic[t]);
            vp[t] = __ldg(r + ip[t]);
        }
#pragma unroll
        for (int jj = 0; jj < 3; jj++) {
            int tL = 2 - jj;
            float wv = ac_[tL] * vc[tL] + bc_[tL + 1] * vc[tL + 1];
            acc[jj] += fabsf(l - wv);
            float wv2 = apw[tL] * vp[tL] + bpw[tL + 1] * vp[tL + 1];
            acc[jj + 3] += fabsf(l - wv2);
        }
    }
    g_sumabs[idx] = sa;
#pragma unroll
    for (int j = 0; j < 6; j++) g_cv[j][idx] = acc[j];
}

// ---------------- kernel 3: fused 1x1 convs (writes padded hA) ----------------
__global__ __launch_bounds__(128) void k_fused1x1(const float* __restrict__ cur,
                                                  const float* __restrict__ w_dec,
                                                  const float* __restrict__ b_dec,
                                                  const float* __restrict__ w0,
                                                  const float* __restrict__ b0) {
    __shared__ float s_wd[64 * 16];
    __shared__ float s_w0[64 * 32];
    __shared__ float s_bd[16], s_b0[32];
    for (int t = threadIdx.x; t < 64 * 16; t += blockDim.x) {
        int c = t >> 4, o = t & 15;
        s_wd[t] = w_dec[o * 64 + c];
    }
    for (int t = threadIdx.x; t < 64 * 32; t += blockDim.x) {
        int c = t >> 5, o = t & 31;
        s_w0[t] = w0[o * 64 + c];
    }
    if (threadIdx.x < 16) s_bd[threadIdx.x] = b_dec[threadIdx.x];
    if (threadIdx.x < 32) s_b0[threadIdx.x] = b0[threadIdx.x];
    __syncthreads();

    int idx = blockIdx.x * blockDim.x + threadIdx.x;
    if (idx >= NT) return;
    int wt = idx % Wt;
    int ht = (idx / Wt) % Ht;
    int b = idx / TIL;

    float ac[16], ap[16];
#pragma unroll
    for (int o = 0; o < 16; o++) { ac[o] = s_bd[o]; ap[o] = s_bd[o]; }

#pragma unroll
    for (int c = 0; c < 64; c++) {
        int ry = (c >> 2) & 3, rx = c & 3;
        int fidx = (b * H + 4 * ht + ry) * W + 4 * wt + rx;
        float vc, vp;
        if (c < 16) {
            float s = g_sumabs[fidx];
            vc = s; vp = s;
        } else {
            int k = (c - 16) >> 4;
            vc = g_cv[k][fidx];
            vp = g_cv[3 + k][fidx];
        }
        const float4* wp = (const float4*)&s_wd[c * 16];
#pragma unroll
        for (int q = 0; q < 4; q++) {
            float4 w4 = wp[q];
            ac[4 * q + 0] += w4.x * vc; ac[4 * q + 1] += w4.y * vc;
            ac[4 * q + 2] += w4.z * vc; ac[4 * q + 3] += w4.w * vc;
            ap[4 * q + 0] += w4.x * vp; ap[4 * q + 1] += w4.y * vp;
            ap[4 * q + 2] += w4.z * vp; ap[4 * q + 3] += w4.w * vp;
        }
    }
#pragma unroll
    for (int o = 0; o < 16; o++) {
        ac[o] = ac[o] >= 0.f ? ac[o] : 0.2f * ac[o];
        ap[o] = ap[o] >= 0.f ? ap[o] : 0.2f * ap[o];
    }

    float ah[32];
#pragma unroll
    for (int o = 0; o < 32; o++) ah[o] = s_b0[o];
    int tb = b * 16 * TIL + ht * Wt + wt;
#pragma unroll
    for (int c = 0; c < 64; c++) {
        float v;
        if (c < 16)       v = cur[tb + c * TIL];
        else if (c < 32)  v = ac[c - 16];
        else if (c < 48)  v = g_upprev[tb + (c - 32) * TIL];
        else              v = ap[c - 48];
        const float4* wp = (const float4*)&s_w0[c * 32];
#pragma unroll
        for (int q = 0; q < 8; q++) {
            float4 w4 = wp[q];
            ah[4 * q + 0] += w4.x * v; ah[4 * q + 1] += w4.y * v;
            ah[4 * q + 2] += w4.z * v; ah[4 * q + 3] += w4.w * v;
        }
    }
    int ob = b * 32 * PS + (ht + 1) * PW + (wt + 1);
#pragma unroll
    for (int o = 0; o < 32; o++) {
        float v = ah[o];
        v = v >= 0.f ? v : 0.2f * v;
        g_hA[ob + o * PS] = v;
    }
}

// ---------------- kernel 4: 3x3 conv, constant weights, padded I/O, f32x2 ----
// Block (32,2)=64 threads: tile 32x4, 2 rows/thread, OCB channels per block.
// Weights come from the constant bank c_w2 (separate constant port -> zero
// L1 weight traffic, no smem staging, no staging barrier).
template <int OCT, int OCB, int NSLICE, bool RES, bool LEAKY, bool PADOUT>
__global__ __launch_bounds__(64, 8) void k_conv3(const float* __restrict__ in,
                                                 const float* __restrict__ res,
                                                 const float* __restrict__ bias,
                                                 float* __restrict__ out) {
    constexpr int NP = OCB / 2;
    constexpr int NQ = OCB / 4;
    constexpr int SLQ = 288 * OCB / 4;    // ulonglong2 elements per slice

    int tx = threadIdx.x, ty = threadIdx.y;
    int x0 = blockIdx.x * 32, y0 = blockIdx.y * 4;
    int b = blockIdx.z / NSLICE;
    int slice = blockIdx.z % NSLICE;
    int o_base = min(slice * OCB, OCT - OCB);
    int wsl = slice * SLQ;

    uint64_t acc[2][NP];
#pragma unroll
    for (int q = 0; q < NP; q++) {
        uint64_t bp = pack2(__ldg(bias + o_base + 2 * q), __ldg(bias + o_base + 2 * q + 1));
        acc[0][q] = bp;
        acc[1][q] = bp;
    }

    int yloc = ty * 2;
    const float* pin = in + (size_t)(b * 32) * PS + (y0 + yloc) * PW + (x0 + tx);

    float pf[12];
#pragma unroll
    for (int r = 0; r < 4; r++)
#pragma unroll
        for (int c = 0; c < 3; c++)
            pf[r * 3 + c] = __ldg(pin + r * PW + c);

#pragma unroll 2
    for (int ci = 0; ci < 32; ci++) {
        uint64_t iv[4][3];
#pragma unroll
        for (int r = 0; r < 4; r++)
#pragma unroll
            for (int c = 0; c < 3; c++)
                iv[r][c] = bcast2(pf[r * 3 + c]);

        pin += PS;
        if (ci < 31) {
#pragma unroll
            for (int r = 0; r < 4; r++)
#pragma unroll
                for (int c = 0; c < 3; c++)
                    pf[r * 3 + c] = __ldg(pin + r * PW + c);
        }

#pragma unroll
        for (int t = 0; t < 9; t++) {
            int dr = t / 3, dc = t % 3;
            int wbase = wsl + (ci * 9 + t) * NQ;
#pragma unroll
            for (int q = 0; q < NQ; q++) {
                ulonglong2 w2 = c_w2[wbase + q];
                ffma2(acc[0][2 * q],     iv[dr][dc],     w2.x);
                ffma2(acc[0][2 * q + 1], iv[dr][dc],     w2.y);
                ffma2(acc[1][2 * q],     iv[dr + 1][dc], w2.x);
                ffma2(acc[1][2 * q + 1], iv[dr + 1][dc], w2.y);
            }
        }
    }

    int x = x0 + tx;
#pragma unroll
    for (int r = 0; r < 2; r++) {
        int y = y0 + yloc + r;
#pragma unroll
        for (int q = 0; q < NP; q++) {
            float v0, v1;
            unpack2(acc[r][q], v0, v1);
            int o0 = o_base + 2 * q, o1 = o0 + 1;
            if (RES) v0 += res[(size_t)(b * 32 + o0) * PS + (y + 1) * PW + (x + 1)];
            if (LEAKY) v0 = v0 >= 0.f ? v0 : 0.2f * v0;
            if (RES) v1 += res[(size_t)(b * 32 + o1) * PS + (y + 1) * PW + (x + 1)];
            if (LEAKY) v1 = v1 >= 0.f ? v1 : 0.2f * v1;
            if (PADOUT) {
                out[(size_t)(b * 32 + o0) * PS + (y + 1) * PW + (x + 1)] = v0;
                out[(size_t)(b * 32 + o1) * PS + (y + 1) * PW + (x + 1)] = v1;
            } else {
                out[((b * OCT + o0) * Ht + y) * Wt + x] = v0;
                out[((b * OCT + o1) * Ht + y) * Wt + x] = v1;
            }
        }
    }
}

// ---------------- kernel 5: epilogue ----------------
__global__ void k_final(const float* __restrict__ cur, float* __restrict__ out) {
    int idx = blockIdx.x * blockDim.x + threadIdx.x;
    if (idx >= NT) return;
    int wt = idx % Wt;
    int ht = (idx / Wt) % Ht;
    int b = idx / TIL;
    int p = ht * Wt + wt;
    const float* u = g_u + b * 34 * TIL + p;
    float c0 = u[0];
    float c1 = u[TIL];
    bool pick_cur = (c1 > c0);

    float* o1 = out + b * 16 * TIL + p;
    float* o2 = out + B * 16 * TIL + b * 17 * TIL + p;
    float* o3 = out + B * 16 * TIL + B * 17 * TIL + b * 17 * TIL + p;
#pragma unroll
    for (int c = 0; c < 16; c++) {
        float uc = cur[b * 16 * TIL + c * TIL + p] + u[(18 + c) * TIL];
        float up = g_upprev[b * 16 * TIL + c * TIL + p] + u[(2 + c) * TIL];
        if (c == 0) { uc = fmaxf(uc, 0.f); up = fmaxf(up, 0.f); }
        o1[c * TIL] = pick_cur ? uc : up;
        o2[c * TIL] = uc;
        o3[c * TIL] = up;
    }
    o2[16 * TIL] = c1;
    o3[16 * TIL] = c0;
}

// ---------------- launch ----------------
extern "C" void kernel_launch(void* const* d_in, const int* in_sizes, int n_in,
                              void* d_out, int out_size) {
    const float* fea_l  = (const float*)d_in[0];
    const float* fea_r  = (const float*)d_in[1];
    const float* cur    = (const float*)d_in[2];
    const float* prev   = (const float*)d_in[3];
    const float* w_dec  = (const float*)d_in[4];
    const float* b_dec  = (const float*)d_in[5];
    const float* w0     = (const float*)d_in[6];
    const float* b0     = (const float*)d_in[7];
    const float* w_r0c1 = (const float*)d_in[8];
    const float* b_r0c1 = (const float*)d_in[9];
    const float* w_r0c2 = (const float*)d_in[10];
    const float* b_r0c2 = (const float*)d_in[11];
    const float* w_r1c1 = (const float*)d_in[12];
    const float* b_r1c1 = (const float*)d_in[13];
    const float* w_r1c2 = (const float*)d_in[14];
    const float* b_r1c2 = (const float*)d_in[15];
    const float* w_last = (const float*)d_in[16];
    const float* b_last = (const float*)d_in[17];
    float* out = (float*)d_out;

    void *pA, *pB, *pC, *pU, *pW;
    cudaGetSymbolAddress(&pA, g_hA);
    cudaGetSymbolAddress(&pB, g_hB);
    cudaGetSymbolAddress(&pC, g_hC);
    cudaGetSymbolAddress(&pU, g_u);
    cudaGetSymbolAddress(&pW, g_wt);
    float* hA = (float*)pA;
    float* hB = (float*)pB;
    float* hC = (float*)pC;
    float* uB = (float*)pU;
    float* wS = (float*)pW;

    // transpose all 5 weight sets into scratch
    k_wtrans<<<(2 * 288 * 16 + 127) / 128, 128>>>(w_r0c1, 32, 16, 0);
    k_wtrans<<<(2 * 288 * 16 + 127) / 128, 128>>>(w_r0c2, 32, 16, 9216);
    k_wtrans<<<(2 * 288 * 16 + 127) / 128, 128>>>(w_r1c1, 32, 16, 18432);
    k_wtrans<<<(2 * 288 * 16 + 127) / 128, 128>>>(w_r1c2, 32, 16, 27648);
    k_wtrans<<<(2 * 288 * 20 + 127) / 128, 128>>>(w_last, 34, 20, 36864);

    k_upsample<<<(B * 16 * TIL + 255) / 256, 256>>>(prev);
    k_warpcv<<<(FULL + 127) / 128, 128>>>(fea_l, fea_r, cur);
    k_fused1x1<<<(NT + 127) / 128, 128>>>(cur, w_dec, b_dec, w0, b0);

    dim3 cb(32, 2);
    dim3 cg(Wt / 32, Ht / 4, B * 2);    // (10, 24, 4) = 960 blocks, 64 thr
    constexpr size_t W16 = 2 * 288 * 16 * sizeof(float);   // 36864 B
    constexpr size_t W20 = 2 * 288 * 20 * sizeof(float);   // 46080 B

    cudaMemcpyToSymbolAsync(c_w2, wS + 0, W16, 0, cudaMemcpyDeviceToDevice, 0);
    k_conv3<32, 16, 2, false, true,  true ><<<cg, cb>>>(hA, nullptr, b_r0c1, hB);
    cudaMemcpyToSymbolAsync(c_w2, wS + 9216, W16, 0, cudaMemcpyDeviceToDevice, 0);
    k_conv3<32, 16, 2, true,  true,  true ><<<cg, cb>>>(hB, hA, b_r0c2, hC);
    cudaMemcpyToSymbolAsync(c_w2, wS + 18432, W16, 0, cudaMemcpyDeviceToDevice, 0);
    k_conv3<32, 16, 2, false, true,  true ><<<cg, cb>>>(hC, nullptr, b_r1c1, hB);
    cudaMemcpyToSymbolAsync(c_w2, wS + 27648, W16, 0, cudaMemcpyDeviceToDevice, 0);
    k_conv3<32, 16, 2, true,  true,  true ><<<cg, cb>>>(hB, hC, b_r1c2, hA);
    cudaMemcpyToSymbolAsync(c_w2, wS + 36864, W20, 0, cudaMemcpyDeviceToDevice, 0);
    k_conv3<34, 20, 2, false, false, false><<<cg, cb>>>(hA, nullptr, b_last, uB);

    k_final<<<(NT + 255) / 256, 256>>>(cur, out);
}

// round 17
// speedup vs baseline: 1.3831x; 1.3831x over previous
#include <cuda_runtime.h>
#include <cstdint>

// ---------------- problem constants ----------------
constexpr int B  = 2;
constexpr int C  = 16;
constexpr int H  = 384;
constexpr int W  = 1280;
constexpr int Ht = 96;
constexpr int Wt = 320;
constexpr int HW   = H * W;
constexpr int FULL = B * H * W;
constexpr int TIL  = Ht * Wt;
constexpr int NT   = B * TIL;
constexpr int Hp = 48, Wp = 160;
// padded tile-res planes for the conv trunk (zero halo)
constexpr int PW = Wt + 2;           // 322
constexpr int PH = Ht + 2;           // 98
constexpr int PS = PH * PW;          // 31556

// ---------------- scratch ----------------
__device__ float g_upprev[B * 16 * TIL];
__device__ float g_sumabs[FULL];
__device__ float g_cv[6][FULL];
__device__ float g_hA[B * 32 * PS];   // padded
__device__ float g_hB[B * 32 * PS];   // padded
__device__ float g_hC[B * 32 * PS];   // padded
__device__ float g_u[B * 34 * TIL];   // flat

// ---------------- f32x2 packed helpers ----------------
__device__ __forceinline__ void ffma2(uint64_t& d, uint64_t a, uint64_t b) {
    asm("fma.rn.f32x2 %0, %1, %2, %0;" : "+l"(d) : "l"(a), "l"(b));
}
__device__ __forceinline__ uint64_t pack2(float lo, float hi) {
    uint64_t r;
    asm("mov.b64 %0, {%1, %2};" : "=l"(r) : "f"(lo), "f"(hi));
    return r;
}
__device__ __forceinline__ uint64_t bcast2(float v) {
    uint64_t r;
    asm("mov.b64 %0, {%1, %1};" : "=l"(r) : "f"(v));
    return r;
}
__device__ __forceinline__ void unpack2(uint64_t a, float& lo, float& hi) {
    asm("mov.b64 {%0, %1}, %2;" : "=f"(lo), "=f"(hi) : "l"(a));
}

// ---------------- kernel 1: upsample ----------------
__global__ void k_upsample(const float* __restrict__ prev) {
    int idx = blockIdx.x * blockDim.x + threadIdx.x;
    if (idx >= B * 16 * TIL) return;
    int x = idx % Wt;
    int y = (idx / Wt) % Ht;
    int c = (idx / TIL) % 16;
    int b = idx / (16 * TIL);
    int xh = x >> 1, yh = y >> 1;
    const float* p = prev + (size_t)b * 16 * Hp * Wp;
    int off = yh * Wp + xh;
    float v;
    if (c == 0) {
        float cx = (x & 1) ? 0.5f : -0.5f;
        float cy = (y & 1) ? 0.5f : -0.5f;
        v = 2.0f * (p[off] + cx * p[Hp * Wp + off] + cy * p[2 * Hp * Wp + off]);
    } else {
        v = p[c * Hp * Wp + off];
    }
    g_upprev[idx] = v;
}

// ---------------- kernel 2: fused fea + 6 cost volumes (shared gathers) ------
__global__ __launch_bounds__(128) void k_warpcv(const float* __restrict__ fea_l,
                                                const float* __restrict__ fea_r,
                                                const float* __restrict__ cur) {
    int idx = blockIdx.x * blockDim.x + threadIdx.x;
    if (idx >= FULL) return;
    int x = idx % W;
    int y = (idx / W) % H;
    int b = idx / (H * W);
    int ht = y >> 2, wt = x >> 2;
    float cx = (float)(x & 3) - 1.5f;
    float cy = (float)(y & 3) - 1.5f;

    int toff = b * 16 * TIL + ht * Wt + wt;
    float bc = cur[toff] + cx * cur[toff + TIL] + cy * cur[toff + 2 * TIL];
    float bp = g_upprev[toff] + cx * g_upprev[toff + TIL] + cy * g_upprev[toff + 2 * TIL];

    int   ic[4], ip[4];
    float ac_[4], bc_[4], apw[4], bpw[4];
    {
        float ix = (float)x - bc;
        float f = floorf(ix);
        float wx = ix - f;
        int x0 = (int)f;
#pragma unroll
        for (int t = 0; t < 4; t++) {
            int xi = x0 - 1 + t;
            float ok = (xi >= 0 && xi < W) ? 1.f : 0.f;
            ic[t] = min(max(xi, 0), W - 1);
            ac_[t] = (1.f - wx) * ok;
            bc_[t] = wx * ok;
        }
    }
    {
        float ix = (float)x - bp;
        float f = floorf(ix);
        float wx = ix - f;
        int x0 = (int)f;
#pragma unroll
        for (int t = 0; t < 4; t++) {
            int xi = x0 - 1 + t;
            float ok = (xi >= 0 && xi < W) ? 1.f : 0.f;
            ip[t] = min(max(xi, 0), W - 1);
            apw[t] = (1.f - wx) * ok;
            bpw[t] = wx * ok;
        }
    }

    float acc[6] = {0.f, 0.f, 0.f, 0.f, 0.f, 0.f};
    float sa = 0.f;
    const float* fl = fea_l + (size_t)b * C * HW + y * W + x;
    const float* fr = fea_r + (size_t)b * C * HW + y * W;
#pragma unroll 2
    for (int c = 0; c < C; c++) {
        float l = fl[c * HW];
        sa += fabsf(l);
        const float* r = fr + c * HW;
        float vc[4], vp[4];
#pragma unroll
        for (int t = 0; t < 4; t++) {
            vc[t] = __ldg(r + ic[t]);
            vp[t] = __ldg(r + ip[t]);
        }
#pragma unroll
        for (int jj = 0; jj < 3; jj++) {
            int tL = 2 - jj;
            float wv = ac_[tL] * vc[tL] + bc_[tL + 1] * vc[tL + 1];
            acc[jj] += fabsf(l - wv);
            float wv2 = apw[tL] * vp[tL] + bpw[tL + 1] * vp[tL + 1];
            acc[jj + 3] += fabsf(l - wv2);
        }
    }
    g_sumabs[idx] = sa;
#pragma unroll
    for (int j = 0; j < 6; j++) g_cv[j][idx] = acc[j];
}

// ---------------- kernel 3: fused 1x1 convs (writes padded hA) ----------------
__global__ __launch_bounds__(128) void k_fused1x1(const float* __restrict__ cur,
                                                  const float* __restrict__ w_dec,
                                                  const float* __restrict__ b_dec,
                                                  const float* __restrict__ w0,
                                                  const float* __restrict__ b0) {
    __shared__ float s_wd[64 * 16];
    __shared__ float s_w0[64 * 32];
    __shared__ float s_bd[16], s_b0[32];
    for (int t = threadIdx.x; t < 64 * 16; t += blockDim.x) {
        int c = t >> 4, o = t & 15;
        s_wd[t] = w_dec[o * 64 + c];
    }
    for (int t = threadIdx.x; t < 64 * 32; t += blockDim.x) {
        int c = t >> 5, o = t & 31;
        s_w0[t] = w0[o * 64 + c];
    }
    if (threadIdx.x < 16) s_bd[threadIdx.x] = b_dec[threadIdx.x];
    if (threadIdx.x < 32) s_b0[threadIdx.x] = b0[threadIdx.x];
    __syncthreads();

    int idx = blockIdx.x * blockDim.x + threadIdx.x;
    if (idx >= NT) return;
    int wt = idx % Wt;
    int ht = (idx / Wt) % Ht;
    int b = idx / TIL;

    float ac[16], ap[16];
#pragma unroll
    for (int o = 0; o < 16; o++) { ac[o] = s_bd[o]; ap[o] = s_bd[o]; }

#pragma unroll
    for (int c = 0; c < 64; c++) {
        int ry = (c >> 2) & 3, rx = c & 3;
        int fidx = (b * H + 4 * ht + ry) * W + 4 * wt + rx;
        float vc, vp;
        if (c < 16) {
            float s = g_sumabs[fidx];
            vc = s; vp = s;
        } else {
            int k = (c - 16) >> 4;
            vc = g_cv[k][fidx];
            vp = g_cv[3 + k][fidx];
        }
        const float4* wp = (const float4*)&s_wd[c * 16];
#pragma unroll
        for (int q = 0; q < 4; q++) {
            float4 w4 = wp[q];
            ac[4 * q + 0] += w4.x * vc; ac[4 * q + 1] += w4.y * vc;
            ac[4 * q + 2] += w4.z * vc; ac[4 * q + 3] += w4.w * vc;
            ap[4 * q + 0] += w4.x * vp; ap[4 * q + 1] += w4.y * vp;
            ap[4 * q + 2] += w4.z * vp; ap[4 * q + 3] += w4.w * vp;
        }
    }
#pragma unroll
    for (int o = 0; o < 16; o++) {
        ac[o] = ac[o] >= 0.f ? ac[o] : 0.2f * ac[o];
        ap[o] = ap[o] >= 0.f ? ap[o] : 0.2f * ap[o];
    }

    float ah[32];
#pragma unroll
    for (int o = 0; o < 32; o++) ah[o] = s_b0[o];
    int tb = b * 16 * TIL + ht * Wt + wt;
#pragma unroll
    for (int c = 0; c < 64; c++) {
        float v;
        if (c < 16)       v = cur[tb + c * TIL];
        else if (c < 32)  v = ac[c - 16];
        else if (c < 48)  v = g_upprev[tb + (c - 32) * TIL];
        else              v = ap[c - 48];
        const float4* wp = (const float4*)&s_w0[c * 32];
#pragma unroll
        for (int q = 0; q < 8; q++) {
            float4 w4 = wp[q];
            ah[4 * q + 0] += w4.x * v; ah[4 * q + 1] += w4.y * v;
            ah[4 * q + 2] += w4.z * v; ah[4 * q + 3] += w4.w * v;
        }
    }
    int ob = b * 32 * PS + (ht + 1) * PW + (wt + 1);
#pragma unroll
    for (int o = 0; o < 32; o++) {
        float v = ah[o];
        v = v >= 0.f ? v : 0.2f * v;
        g_hA[ob + o * PS] = v;
    }
}

// ---------------- kernel 4: 3x3 conv, 2 X-pixels/thread, f32x2 ---------------
// Block (32,2)=64 threads: tile 64 wide x 2 tall. Each thread computes 2
// horizontally-adjacent pixels for OCB channels. Input window = 3 rows x
// 4 cols loaded as 6 aligned LDG.64. Each weight LDS.128 feeds 8 FFMA2.
template <int OCT, int OCB, int NSLICE, bool RES, bool LEAKY, bool PADOUT>
__global__ __launch_bounds__(64, 8) void k_conv3(const float* __restrict__ in,
                                                 const float* __restrict__ res,
                                                 const float* __restrict__ w,
                                                 const float* __restrict__ bias,
                                                 float* __restrict__ out) {
    constexpr int NP = OCB / 2;
    constexpr int NQ = OCB / 4;
    __shared__ float s_w[32 * 9 * OCB];

    int tx = threadIdx.x, ty = threadIdx.y;
    int tid = ty * 32 + tx;
    int x0 = blockIdx.x * 64, y0 = blockIdx.y * 2;
    int b = blockIdx.z / NSLICE;
    int slice = blockIdx.z % NSLICE;
    int o_base = min(slice * OCB, OCT - OCB);

    for (int t = tid; t < 32 * 9 * OCB; t += 64) {
        int lo = t % OCB;
        int ct = t / OCB;
        int ci = ct / 9, tap = ct % 9;
        s_w[t] = w[((o_base + lo) * 32 + ci) * 9 + tap];
    }
    __syncthreads();

    uint64_t acc[2][NP];     // [pixel 0/1][channel pair]
#pragma unroll
    for (int q = 0; q < NP; q++) {
        uint64_t bp = pack2(__ldg(bias + o_base + 2 * q), __ldg(bias + o_base + 2 * q + 1));
        acc[0][q] = bp;
        acc[1][q] = bp;
    }

    int xp = x0 + tx * 2;    // unpadded x of pixel 0 (pixel 1 = xp+1)
    int y = y0 + ty;
    // padded window: rows y..y+2, cols xp..xp+3 (aligned float2 pairs)
    const float* pin = in + (size_t)(b * 32) * PS + y * PW + xp;

#pragma unroll 2
    for (int ci = 0; ci < 32; ci++) {
        // load 3x4 window as 6 LDG.64
        uint64_t iv[3][4];
#pragma unroll
        for (int r = 0; r < 3; r++) {
            float2 a = __ldg((const float2*)(pin + r * PW));
            float2 bb = __ldg((const float2*)(pin + r * PW + 2));
            iv[r][0] = bcast2(a.x);
            iv[r][1] = bcast2(a.y);
            iv[r][2] = bcast2(bb.x);
            iv[r][3] = bcast2(bb.y);
        }
        pin += PS;

#pragma unroll
        for (int t = 0; t < 9; t++) {
            int dr = t / 3, dc = t % 3;
            const ulonglong2* wp = (const ulonglong2*)(s_w + ((ci * 9 + t) * OCB));
#pragma unroll
            for (int q = 0; q < NQ; q++) {
                ulonglong2 w2 = wp[q];
                ffma2(acc[0][2 * q],     iv[dr][dc],     w2.x);
                ffma2(acc[0][2 * q + 1], iv[dr][dc],     w2.y);
                ffma2(acc[1][2 * q],     iv[dr][dc + 1], w2.x);
                ffma2(acc[1][2 * q + 1], iv[dr][dc + 1], w2.y);
            }
        }
    }

#pragma unroll
    for (int px = 0; px < 2; px++) {
        int x = xp + px;
#pragma unroll
        for (int q = 0; q < NP; q++) {
            float v0, v1;
            unpack2(acc[px][q], v0, v1);
            int o0 = o_base + 2 * q, o1 = o0 + 1;
            if (RES) v0 += res[(size_t)(b * 32 + o0) * PS + (y + 1) * PW + (x + 1)];
            if (LEAKY) v0 = v0 >= 0.f ? v0 : 0.2f * v0;
            if (RES) v1 += res[(size_t)(b * 32 + o1) * PS + (y + 1) * PW + (x + 1)];
            if (LEAKY) v1 = v1 >= 0.f ? v1 : 0.2f * v1;
            if (PADOUT) {
                out[(size_t)(b * 32 + o0) * PS + (y + 1) * PW + (x + 1)] = v0;
                out[(size_t)(b * 32 + o1) * PS + (y + 1) * PW + (x + 1)] = v1;
            } else {
                out[((b * OCT + o0) * Ht + y) * Wt + x] = v0;
                out[((b * OCT + o1) * Ht + y) * Wt + x] = v1;
            }
        }
    }
}

// ---------------- kernel 5: epilogue ----------------
__global__ void k_final(const float* __restrict__ cur, float* __restrict__ out) {
    int idx = blockIdx.x * blockDim.x + threadIdx.x;
    if (idx >= NT) return;
    int wt = idx % Wt;
    int ht = (idx / Wt) % Ht;
    int b = idx / TIL;
    int p = ht * Wt + wt;
    const float* u = g_u + b * 34 * TIL + p;
    float c0 = u[0];
    float c1 = u[TIL];
    bool pick_cur = (c1 > c0);

    float* o1 = out + b * 16 * TIL + p;
    float* o2 = out + B * 16 * TIL + b * 17 * TIL + p;
    float* o3 = out + B * 16 * TIL + B * 17 * TIL + b * 17 * TIL + p;
#pragma unroll
    for (int c = 0; c < 16; c++) {
        float uc = cur[b * 16 * TIL + c * TIL + p] + u[(18 + c) * TIL];
        float up = g_upprev[b * 16 * TIL + c * TIL + p] + u[(2 + c) * TIL];
        if (c == 0) { uc = fmaxf(uc, 0.f); up = fmaxf(up, 0.f); }
        o1[c * TIL] = pick_cur ? uc : up;
        o2[c * TIL] = uc;
        o3[c * TIL] = up;
    }
    o2[16 * TIL] = c1;
    o3[16 * TIL] = c0;
}

// ---------------- launch ----------------
extern "C" void kernel_launch(void* const* d_in, const int* in_sizes, int n_in,
                              void* d_out, int out_size) {
    const float* fea_l  = (const float*)d_in[0];
    const float* fea_r  = (const float*)d_in[1];
    const float* cur    = (const float*)d_in[2];
    const float* prev   = (const float*)d_in[3];
    const float* w_dec  = (const float*)d_in[4];
    const float* b_dec  = (const float*)d_in[5];
    const float* w0     = (const float*)d_in[6];
    const float* b0     = (const float*)d_in[7];
    const float* w_r0c1 = (const float*)d_in[8];
    const float* b_r0c1 = (const float*)d_in[9];
    const float* w_r0c2 = (const float*)d_in[10];
    const float* b_r0c2 = (const float*)d_in[11];
    const float* w_r1c1 = (const float*)d_in[12];
    const float* b_r1c1 = (const float*)d_in[13];
    const float* w_r1c2 = (const float*)d_in[14];
    const float* b_r1c2 = (const float*)d_in[15];
    const float* w_last = (const float*)d_in[16];
    const float* b_last = (const float*)d_in[17];
    float* out = (float*)d_out;

    void *pA, *pB, *pC, *pU;
    cudaGetSymbolAddress(&pA, g_hA);
    cudaGetSymbolAddress(&pB, g_hB);
    cudaGetSymbolAddress(&pC, g_hC);
    cudaGetSymbolAddress(&pU, g_u);
    float* hA = (float*)pA;
    float* hB = (float*)pB;
    float* hC = (float*)pC;
    float* uB = (float*)pU;

    k_upsample<<<(B * 16 * TIL + 255) / 256, 256>>>(prev);
    k_warpcv<<<(FULL + 127) / 128, 128>>>(fea_l, fea_r, cur);
    k_fused1x1<<<(NT + 127) / 128, 128>>>(cur, w_dec, b_dec, w0, b0);

    dim3 cb(32, 2);
    dim3 cg(Wt / 64, Ht / 2, B * 2);    // (5, 48, 4) = 960 blocks, 64 thr
    k_conv3<32, 16, 2, false, true,  true ><<<cg, cb>>>(hA, nullptr, w_r0c1, b_r0c1, hB);
    k_conv3<32, 16, 2, true,  true,  true ><<<cg, cb>>>(hB, hA, w_r0c2, b_r0c2, hC);
    k_conv3<32, 16, 2, false, true,  true ><<<cg, cb>>>(hC, nullptr, w_r1c1, b_r1c1, hB);
    k_conv3<32, 16, 2, true,  true,  true ><<<cg, cb>>>(hB, hC, w_r1c2, b_r1c2, hA);
    k_conv3<34, 20, 2, false, false, false><<<cg, cb>>>(hA, nullptr, w_last, b_last, uB);
    k_final<<<(NT + 255) / 256, 256>>>(cur, out);
}